// round 2
// baseline (speedup 1.0000x reference)
#include <cuda_runtime.h>
#include <cstdint>

#define BB 4
#define CH 1024
#define HH 50
#define WW 50
#define KK 512
#define NPIX (HH*WW)              // 2500
#define AH 7
#define AW 7
#define GPTS 8                    // AH+1 grid points per axis

// NHWC-transposed features: [B][H][W][C]  (41 MB device-global scratch)
__device__ __align__(16) float FT[BB * HH * WW * CH];

// ---------------------------------------------------------------------------
// Kernel 1: NCHW -> NHWC transpose (per batch: [C, 2500] -> [2500, C])
// ---------------------------------------------------------------------------
__global__ void transpose_kernel(const float* __restrict__ f) {
    __shared__ float tile[32][33];
    int b  = blockIdx.z;
    int p0 = blockIdx.x * 32;   // pixel index (y*W + x)
    int c0 = blockIdx.y * 32;   // channel
    int tx = threadIdx.x, ty = threadIdx.y;   // 32 x 8

    const float* fb = f + (size_t)b * CH * NPIX;
    #pragma unroll
    for (int i = ty; i < 32; i += 8) {
        int c = c0 + i;
        int p = p0 + tx;
        tile[i][tx] = (p < NPIX) ? fb[(size_t)c * NPIX + p] : 0.0f;
    }
    __syncthreads();
    float* ob = FT + (size_t)b * NPIX * CH;
    #pragma unroll
    for (int i = ty; i < 32; i += 8) {
        int p = p0 + i;
        int c = c0 + tx;
        if (p < NPIX) ob[(size_t)p * CH + c] = tile[tx][i];
    }
}

// ---------------------------------------------------------------------------
// Kernel 2: fused RoIAlign (8x8 bilinear grid) + 2x2 avg pool -> (K,C,7,7)
// One block per roi. 512 threads, 2 channels per thread (float2 path).
// Pooled 7x7 accumulator lives in registers; staged smem writes for
// fully-coalesced float4 output stores.
// ---------------------------------------------------------------------------
__global__ __launch_bounds__(512, 1)
void roi_pool_kernel(const float* __restrict__ rois, float* __restrict__ out) {
    const int k   = blockIdx.x;
    const int tid = threadIdx.x;

    __shared__ __align__(16) float sbuf[128 * 49];   // 25088 B write staging
    __shared__ float s_wx[GPTS], s_wy[GPTS], s_vx[GPTS], s_vy[GPTS];
    __shared__ int   s_x0[GPTS], s_y0[GPTS];
    __shared__ int   s_b;

    if (tid < GPTS) {
        float x1 = rois[k * 5 + 1] * 0.0625f;
        float y1 = rois[k * 5 + 2] * 0.0625f;
        float x2 = rois[k * 5 + 3] * 0.0625f;
        float y2 = rois[k * 5 + 4] * 0.0625f;
        float bh = fmaxf(y2 - y1, 0.0f) * (1.0f / 7.0f);
        float bw = fmaxf(x2 - x1, 0.0f) * (1.0f / 7.0f);
        float xv = x1 + (float)tid * bw;
        float yv = y1 + (float)tid * bh;
        s_vx[tid] = (xv >= 0.0f && xv < (float)WW) ? 1.0f : 0.0f;
        s_vy[tid] = (yv >= 0.0f && yv < (float)HH) ? 1.0f : 0.0f;
        int x0 = (int)floorf(xv);  x0 = min(max(x0, 0), WW - 2);
        int y0 = (int)floorf(yv);  y0 = min(max(y0, 0), HH - 2);
        s_x0[tid] = x0;  s_y0[tid] = y0;
        s_wx[tid] = xv - (float)x0;
        s_wy[tid] = yv - (float)y0;
        if (tid == 0) s_b = (int)rois[k * 5 + 0];
    }
    __syncthreads();

    const int c0 = tid * 2;
    const float* bptr = FT + (size_t)s_b * (NPIX * CH) + c0;

    float2 acc[49];
    #pragma unroll
    for (int i = 0; i < 49; i++) { acc[i].x = 0.0f; acc[i].y = 0.0f; }

    #pragma unroll
    for (int gy = 0; gy < GPTS; gy++) {
        const int   y0 = s_y0[gy];
        const float wy = s_wy[gy];
        const float vy = s_vy[gy];
        const float* rp = bptr + (size_t)y0 * (WW * CH);
        #pragma unroll
        for (int gx = 0; gx < GPTS; gx++) {
            const int   x0 = s_x0[gx];
            const float wx = s_wx[gx];
            const float sc = 0.25f * vy * s_vx[gx];

            const float* p = rp + x0 * CH;
            float2 v00 = *(const float2*)(p);
            float2 v01 = *(const float2*)(p + CH);
            float2 v10 = *(const float2*)(p + WW * CH);
            float2 v11 = *(const float2*)(p + WW * CH + CH);

            float w00 = (1.0f - wy) * (1.0f - wx);
            float w01 = (1.0f - wy) * wx;
            float w10 = wy * (1.0f - wx);
            float w11 = wy * wx;

            float ax = (v00.x * w00 + v01.x * w01 + v10.x * w10 + v11.x * w11) * sc;
            float ay = (v00.y * w00 + v01.y * w01 + v10.y * w10 + v11.y * w11) * sc;

            // scatter into up to 4 pooled cells (indices compile-time after unroll)
            if (gy >= 1 && gx >= 1) { acc[(gy-1)*7 + (gx-1)].x += ax; acc[(gy-1)*7 + (gx-1)].y += ay; }
            if (gy >= 1 && gx <  7) { acc[(gy-1)*7 +  gx   ].x += ax; acc[(gy-1)*7 +  gx   ].y += ay; }
            if (gy <  7 && gx >= 1) { acc[ gy   *7 + (gx-1)].x += ax; acc[ gy   *7 + (gx-1)].y += ay; }
            if (gy <  7 && gx <  7) { acc[ gy   *7 +  gx   ].x += ax; acc[ gy   *7 +  gx   ].y += ay; }
        }
    }

    // ---- staged, coalesced output writes -------------------------------
    // Per-roi output is a contiguous run of CH*49 = 50176 floats.
    // Stage 128 channels (6272 floats) at a time in smem, then blast out
    // with float4 stores.
    float* outk = out + (size_t)k * (CH * 49);
    for (int chunk = 0; chunk < 8; chunk++) {
        if ((tid >> 6) == chunk) {
            int cl = c0 - chunk * 128;   // 0..126, even
            #pragma unroll
            for (int i = 0; i < 49; i++) {
                sbuf[(cl    ) * 49 + i] = acc[i].x;
                sbuf[(cl + 1) * 49 + i] = acc[i].y;
            }
        }
        __syncthreads();
        const float4* s4 = (const float4*)sbuf;
        float4* o4 = (float4*)(outk + chunk * 6272);
        for (int i = tid; i < 1568; i += 512) o4[i] = s4[i];
        __syncthreads();
    }
}

// ---------------------------------------------------------------------------
extern "C" void kernel_launch(void* const* d_in, const int* in_sizes, int n_in,
                              void* d_out, int out_size) {
    const float* features = (const float*)d_in[0];
    const float* rois     = (const float*)d_in[1];
    float* out            = (float*)d_out;

    dim3 tgrid((NPIX + 31) / 32, CH / 32, BB);   // (79, 32, 4)
    transpose_kernel<<<tgrid, dim3(32, 8)>>>(features);
    roi_pool_kernel<<<KK, 512>>>(rois, out);
}